// round 3
// baseline (speedup 1.0000x reference)
#include <cuda_runtime.h>

typedef unsigned long long u64;
typedef unsigned int u32;

#define NB 16
#define NPT 4096
#define NS 1024
#define NK 32
#define NCHUNKS 4096      /* (NB*NS)/4 centroid-chunks */
#define P0SLABS 256       /* 65536 points / 256 per slab */
#define NBLOCKS 148
#define SMEMB 118784      /* pad to force 1 block/SM (2x > 228KB) */

// ---------------- device scratch ----------------
__device__ __align__(16) float g_P0[NB * NPT * 64];
__device__ __align__(16) float g_W0x[3 * 64];
__device__ __align__(16) float g_W0p[64 * 64];
__device__ __align__(16) float g_B0[64];
__device__ __align__(16) float g_W1[64 * 64];
__device__ __align__(16) float g_B1[64];
__device__ __align__(16) float g_W2[64 * 128];
__device__ __align__(16) float g_B2[128];
__device__ int g_prog[NB];      // centroids published per batch
__device__ u32 g_chunk;         // work-steal counter for KNN+MLP chunks
__device__ u32 g_p0chunk;       // work-steal counter for P0 slabs
__device__ u32 g_p0fin;         // completed P0 slabs

// ---------------- packed f32x2 helpers ----------------
__device__ __forceinline__ u64 ffma2(u64 a, u64 b, u64 c) {
    u64 d; asm("fma.rn.f32x2 %0, %1, %2, %3;" : "=l"(d) : "l"(a), "l"(b), "l"(c)); return d;
}
__device__ __forceinline__ u64 add2(u64 a, u64 b) {
    u64 d; asm("add.rn.f32x2 %0, %1, %2;" : "=l"(d) : "l"(a), "l"(b)); return d;
}
__device__ __forceinline__ u64 mul2(u64 a, u64 b) {
    u64 d; asm("mul.rn.f32x2 %0, %1, %2;" : "=l"(d) : "l"(a), "l"(b)); return d;
}
__device__ __forceinline__ u64 dup2(float x) {
    u64 r; asm("mov.b64 %0, {%1, %1};" : "=l"(r) : "f"(x)); return r;
}
__device__ __forceinline__ u64 pack2f(float lo, float hi) {
    u64 r; asm("mov.b64 %0, {%1, %2};" : "=l"(r) : "f"(lo), "f"(hi)); return r;
}
__device__ __forceinline__ u64 packkey(u32 lo, u32 hi) {
    u64 r; asm("mov.b64 %0, {%1, %2};" : "=l"(r) : "r"(lo), "r"(hi)); return r;
}
__device__ __forceinline__ void unpack2(u64 a, float& lo, float& hi) {
    asm("mov.b64 {%0, %1}, %2;" : "=f"(lo), "=f"(hi) : "l"(a));
}

extern __shared__ float dynbuf[];

// shared-memory layout (floats) for worker phase
#define OFF_ACT   0        /* 64 x 132 = 8448 ; also W0p(4096)+B0(64) during P0 */
#define OFF_W1    8448     /* 4096 */
#define OFF_W2    12544    /* 8192 */
#define OFF_B1    20736    /* 64   */
#define OFF_B2    20800    /* 128  */
#define OFF_W0X   20928    /* 192  */
#define OFF_PMAX  21120    /* 2048 */
#define OFF_IDX   23168    /* 128 ints */
#define OFF_KKEY  23296    /* 16 u64 = 32 floats */
#define OFF_MISC  23328    /* 4 u32 */

// ---------------- kernel 1: fold BN into weights + reset counters ----------------
__global__ void prep_kernel(
    const float* w0, const float* cb0, const float* g0, const float* b0, const float* m0, const float* v0,
    const float* w1, const float* cb1, const float* g1, const float* b1, const float* m1, const float* v1,
    const float* w2, const float* cb2, const float* g2, const float* b2, const float* m2, const float* v2)
{
    int o = threadIdx.x;
    if (o == 0) { g_chunk = 0; g_p0chunk = 0; g_p0fin = 0; }
    if (o < NB) g_prog[o] = 0;
    if (o < 64) {
        float s0 = g0[o] / sqrtf(v0[o] + 1e-5f);
        g_B0[o] = (cb0[o] - m0[o]) * s0 + b0[o];
        for (int i = 0; i < 3; i++)  g_W0x[i * 64 + o] = w0[o * 67 + i] * s0;
        for (int c = 0; c < 64; c++) g_W0p[c * 64 + o] = w0[o * 67 + 3 + c] * s0;
        float s1 = g1[o] / sqrtf(v1[o] + 1e-5f);
        g_B1[o] = (cb1[o] - m1[o]) * s1 + b1[o];
        for (int i = 0; i < 64; i++) g_W1[i * 64 + o] = w1[o * 64 + i] * s1;
    }
    if (o < 128) {
        float s2 = g2[o] / sqrtf(v2[o] + 1e-5f);
        g_B2[o] = (cb2[o] - m2[o]) * s2 + b2[o];
        for (int i = 0; i < 64; i++) g_W2[i * 128 + o] = w2[o * 64 + i] * s2;
    }
}

// ---------------- FPS phase (blocks 0..15) ----------------
__device__ void fps_phase(const float* __restrict__ xyz, float* __restrict__ out_newxyz)
{
    float* sX = dynbuf;
    float* sY = dynbuf + NPT;
    float* sZ = dynbuf + 2 * NPT;
    u64* sKey = (u64*)(dynbuf + 3 * NPT);   // [2][8]

    int b = blockIdx.x, t = threadIdx.x;
    const float* xb = xyz + (size_t)b * NPT * 3;

    float fx[16], fy[16], fz[16], dd[16];
    u32 nlo[16];
#pragma unroll
    for (int j = 0; j < 16; j++) {
        int n = t + 256 * j;
        fx[j] = xb[n * 3 + 0]; fy[j] = xb[n * 3 + 1]; fz[j] = xb[n * 3 + 2];
        sX[n] = fx[j]; sY[n] = fy[j]; sZ[n] = fz[j];
        dd[j] = 1e10f;
        nlo[j] = ~(u32)n;
    }
    u64 PX[8], PY[8], PZ[8];
#pragma unroll
    for (int jp = 0; jp < 8; jp++) {
        PX[jp] = pack2f(fx[2 * jp], fx[2 * jp + 1]);
        PY[jp] = pack2f(fy[2 * jp], fy[2 * jp + 1]);
        PZ[jp] = pack2f(fz[2 * jp], fz[2 * jp + 1]);
    }
    __syncthreads();

    float cx = sX[0], cy = sY[0], cz = sZ[0];
    if (t == 0) {
        float* o0 = out_newxyz + (size_t)b * NS * 3;
        o0[0] = cx; o0[1] = cy; o0[2] = cz;
    }

    int lane = t & 31, w = t >> 5;
    for (int it = 0; it < NS - 1; it++) {
        u64 ncx = dup2(-cx), ncy = dup2(-cy), ncz = dup2(-cz);
        u64 best = 0;
#pragma unroll
        for (int jp = 0; jp < 8; jp++) {
            // IEEE-identical to reference order (dx^2+dy^2)+dz^2, no FMA contraction
            u64 ax = add2(PX[jp], ncx); u64 sx = mul2(ax, ax);
            u64 ay = add2(PY[jp], ncy); u64 sy = mul2(ay, ay);
            u64 az = add2(PZ[jp], ncz); u64 sz = mul2(az, az);
            u64 s = add2(add2(sx, sy), sz);
            float da, db_; unpack2(s, da, db_);
            float n0 = fminf(dd[2 * jp], da);      dd[2 * jp] = n0;
            float n1 = fminf(dd[2 * jp + 1], db_); dd[2 * jp + 1] = n1;
            u64 k0 = packkey(nlo[2 * jp], __float_as_uint(n0));
            u64 k1 = packkey(nlo[2 * jp + 1], __float_as_uint(n1));
            u64 km = (k0 > k1) ? k0 : k1;
            best = (km > best) ? km : best;
        }
        u32 hi = (u32)(best >> 32);
        u32 H = __reduce_max_sync(0xffffffffu, hi);
        u32 cand = (hi == H) ? (u32)best : 0u;
        u32 L = __reduce_max_sync(0xffffffffu, cand);
        if (lane == 0) sKey[(it & 1) * 8 + w] = ((u64)H << 32) | (u64)L;
        __syncthreads();
        u64 g = sKey[(it & 1) * 8];
#pragma unroll
        for (int q = 1; q < 8; q++) { u64 k2 = sKey[(it & 1) * 8 + q]; g = (k2 > g) ? k2 : g; }
        int n = (int)((~(u32)g) & (NPT - 1));
        cx = sX[n]; cy = sY[n]; cz = sZ[n];
        if (t == 0) {
            float* oo = out_newxyz + ((size_t)b * NS + it + 1) * 3;
            oo[0] = cx; oo[1] = cy; oo[2] = cz;
            if (((it + 2) & 3) == 0) {               // publish every 4 centroids
                __threadfence();
                *(volatile int*)&g_prog[b] = it + 2;
            }
        }
    }
}

// ---------------- KNN for one centroid (group of 128 threads, named barrier) ----------------
__device__ __forceinline__ void knn_one(
    const float* __restrict__ xyz, const float* __restrict__ out,
    int b, int cent, int barid, int tl, u64* sK /* 2x4 */, int* idxout)
{
    int sgc = b * NS + cent;
    float cx = __ldcg(out + (size_t)sgc * 3 + 0);
    float cy = __ldcg(out + (size_t)sgc * 3 + 1);
    float cz = __ldcg(out + (size_t)sgc * 3 + 2);
    const float* xb = xyz + (size_t)b * NPT * 3;

    float d[32];
#pragma unroll
    for (int j = 0; j < 32; j++) {
        int n = tl + 128 * j;
        float dx = __ldg(xb + n * 3 + 0) - cx;
        float dy = __ldg(xb + n * 3 + 1) - cy;
        float dz = __ldg(xb + n * 3 + 2) - cz;
        d[j] = __fadd_rn(__fadd_rn(__fmul_rn(dx, dx), __fmul_rn(dy, dy)), __fmul_rn(dz, dz));
    }
    u64 lk = ~0ull;
#pragma unroll
    for (int j = 0; j < 32; j++) {
        u64 key = ((u64)__float_as_uint(d[j]) << 32) | (u32)(tl + 128 * j);
        lk = (key < lk) ? key : lk;
    }
    int lane = tl & 31, w = tl >> 5;
    for (int r = 0; r < NK; r++) {
        u32 hi = (u32)(lk >> 32);
        u32 H = __reduce_min_sync(0xffffffffu, hi);
        u32 cand = (hi == H) ? (u32)lk : 0xffffffffu;
        u32 L = __reduce_min_sync(0xffffffffu, cand);
        if (lane == 0) sK[(r & 1) * 4 + w] = ((u64)H << 32) | (u64)L;
        asm volatile("bar.sync %0, %1;" :: "r"(barid), "r"(128) : "memory");
        u64 gg = sK[(r & 1) * 4];
#pragma unroll
        for (int q = 1; q < 4; q++) { u64 k2 = sK[(r & 1) * 4 + q]; gg = (k2 < gg) ? k2 : gg; }
        if (tl == 0) idxout[r] = (int)((u32)gg);
        if (lk == gg) {
#pragma unroll
            for (int j = 0; j < 32; j++) {
                u64 key = ((u64)__float_as_uint(d[j]) << 32) | (u32)(tl + 128 * j);
                if (key == gg) d[j] = __uint_as_float(0x7f800000u);
            }
            lk = ~0ull;
#pragma unroll
            for (int j = 0; j < 32; j++) {
                u64 key = ((u64)__float_as_uint(d[j]) << 32) | (u32)(tl + 128 * j);
                lk = (key < lk) ? key : lk;
            }
        }
    }
}

// ---------------- worker main: P0 (work-stolen) then {KNN -> MLP} chunks ----------------
__device__ void worker_main(const float* __restrict__ xyz, const float* __restrict__ points,
                            float* __restrict__ out)
{
    float* sAct  = dynbuf + OFF_ACT;
    float* sW1   = dynbuf + OFF_W1;
    float* sW2   = dynbuf + OFF_W2;
    float* sB1   = dynbuf + OFF_B1;
    float* sB2   = dynbuf + OFF_B2;
    float* sW0x  = dynbuf + OFF_W0X;
    float* sPmax = dynbuf + OFF_PMAX;
    int*   sIdx  = (int*)(dynbuf + OFF_IDX);
    u64*   sKb   = (u64*)(dynbuf + OFF_KKEY);
    volatile u32* sMisc = (volatile u32*)(dynbuf + OFF_MISC);

    int t = threadIdx.x;

    // load weights (sW0p+B0 into sAct region, used only during P0)
    for (int i = t; i < 4096; i += 256) sW1[i] = g_W1[i];
    for (int i = t; i < 8192; i += 256) sW2[i] = g_W2[i];
    if (t < 64)  sB1[t] = g_B1[t];
    if (t < 128) sB2[t] = g_B2[t];
    if (t < 192) sW0x[t] = g_W0x[t];
    for (int i = t; i < 64 * 64; i += 256) sAct[i] = g_W0p[i];
    if (t < 64) sAct[4096 + t] = g_B0[t];
    __syncthreads();

    // ---- P0: work-stolen slabs of 256 points ----
    for (;;) {
        if (t == 0) sMisc[0] = atomicAdd(&g_p0chunk, 1);
        __syncthreads();
        u32 slab = sMisc[0];
        if (slab >= P0SLABS) break;
        int pid = (int)slab * 256 + t;
        {
            float xr[64];
            const float4* prr = (const float4*)(points + (size_t)pid * 64);
#pragma unroll
            for (int q = 0; q < 16; q++) {
                float4 v = __ldg(prr + q);
                xr[4 * q + 0] = v.x; xr[4 * q + 1] = v.y; xr[4 * q + 2] = v.z; xr[4 * q + 3] = v.w;
            }
            u64 acc[32];
            const u64* bb = (const u64*)(sAct + 4096);
#pragma unroll
            for (int q = 0; q < 32; q++) acc[q] = bb[q];
#pragma unroll
            for (int c = 0; c < 64; c++) {
                u64 xi = dup2(xr[c]);
                const ulonglong2* wr = (const ulonglong2*)(sAct + c * 64);
#pragma unroll
                for (int q = 0; q < 16; q++) {
                    ulonglong2 wv = wr[q];
                    acc[2 * q]     = ffma2(xi, wv.x, acc[2 * q]);
                    acc[2 * q + 1] = ffma2(xi, wv.y, acc[2 * q + 1]);
                }
            }
            ulonglong2* op = (ulonglong2*)(g_P0 + (size_t)pid * 64);
#pragma unroll
            for (int q = 0; q < 16; q++) op[q] = make_ulonglong2(acc[2 * q], acc[2 * q + 1]);
        }
        __threadfence();
        __syncthreads();
        if (t == 0) atomicAdd(&g_p0fin, 1);
    }
    // gate: all P0 slabs complete
    if (t == 0) { while (*(volatile u32*)&g_p0fin < (u32)P0SLABS) __nanosleep(128); }
    __syncthreads();
    __threadfence();

    // ---- chunk loop: 4 centroids per chunk ----
    for (;;) {
        if (t == 0) sMisc[1] = atomicAdd(&g_chunk, 1);
        __syncthreads();
        u32 c = sMisc[1];
        if (c >= NCHUNKS) break;
        int b = (int)(c & (NB - 1));
        int s0 = (int)(c >> 4) * 4;
        if (t == 0) { while (*(volatile int*)&g_prog[b] < s0 + 4) __nanosleep(128); }
        __syncthreads();
        __threadfence();

        // ---- KNN: 2 groups x 128 threads, 2 centroids each ----
        {
            int g = t >> 7, tl = t & 127;
            for (int ci = 0; ci < 2; ci++) {
                int cl = g * 2 + ci;
                knn_one(xyz, out, b, s0 + cl, g + 1, tl, sKb + g * 8, sIdx + cl * 32);
            }
        }
        __syncthreads();

        // ---- MLP: layer 0 -> sAct[64][132] ----
        {
            int p = t & 127, h = t >> 7;
            int sgp = b * NS + s0 + (p >> 5);
            int n = sIdx[p];
            float ccx = __ldcg(out + (size_t)sgp * 3 + 0);
            float ccy = __ldcg(out + (size_t)sgp * 3 + 1);
            float ccz = __ldcg(out + (size_t)sgp * 3 + 2);
            const float* xp = xyz + ((size_t)b * NPT + n) * 3;
            float gx = xp[0] - ccx, gy = xp[1] - ccy, gz = xp[2] - ccz;
            u64 dgx = dup2(gx), dgy = dup2(gy), dgz = dup2(gz);
            const ulonglong2* pr  = (const ulonglong2*)(g_P0 + ((size_t)b * NPT + n) * 64 + h * 32);
            const ulonglong2* wxa = (const ulonglong2*)(sW0x + h * 32);
            const ulonglong2* wxb = (const ulonglong2*)(sW0x + 64 + h * 32);
            const ulonglong2* wxc = (const ulonglong2*)(sW0x + 128 + h * 32);
#pragma unroll
            for (int q = 0; q < 8; q++) {
                ulonglong2 pv = pr[q];   // plain load (coherent with same-kernel writes)
                ulonglong2 wa = wxa[q], wb = wxb[q], wc = wxc[q];
                u64 a0 = ffma2(dgx, wa.x, pv.x); a0 = ffma2(dgy, wb.x, a0); a0 = ffma2(dgz, wc.x, a0);
                u64 a1 = ffma2(dgx, wa.y, pv.y); a1 = ffma2(dgy, wb.y, a1); a1 = ffma2(dgz, wc.y, a1);
                float v0, v1, v2, v3;
                unpack2(a0, v0, v1); unpack2(a1, v2, v3);
                int j0 = h * 32 + q * 4;
                sAct[(j0 + 0) * 132 + p] = fmaxf(v0, 0.f);
                sAct[(j0 + 1) * 132 + p] = fmaxf(v1, 0.f);
                sAct[(j0 + 2) * 132 + p] = fmaxf(v2, 0.f);
                sAct[(j0 + 3) * 132 + p] = fmaxf(v3, 0.f);
            }
        }
        __syncthreads();

        int mt = t >> 4, nt = t & 15;

        // ---- layer 1: thread tile 8M x 4N ----
        u64 acc[4][4];
#pragma unroll
        for (int nn = 0; nn < 4; nn++) {
            u64 bz = dup2(sB1[nt * 4 + nn]);
            acc[nn][0] = bz; acc[nn][1] = bz; acc[nn][2] = bz; acc[nn][3] = bz;
        }
        {
            const ulonglong2* A  = (const ulonglong2*)(sAct + mt * 8);
            const float4* Bw = (const float4*)(sW1 + nt * 4);
#pragma unroll
            for (int k = 0; k < 64; k++) {
                ulonglong2 a01 = A[k * 33], a23 = A[k * 33 + 1];
                float4 bw = Bw[k * 16];
                u64 b0 = dup2(bw.x), b1 = dup2(bw.y), b2 = dup2(bw.z), b3 = dup2(bw.w);
                acc[0][0] = ffma2(b0, a01.x, acc[0][0]); acc[0][1] = ffma2(b0, a01.y, acc[0][1]);
                acc[0][2] = ffma2(b0, a23.x, acc[0][2]); acc[0][3] = ffma2(b0, a23.y, acc[0][3]);
                acc[1][0] = ffma2(b1, a01.x, acc[1][0]); acc[1][1] = ffma2(b1, a01.y, acc[1][1]);
                acc[1][2] = ffma2(b1, a23.x, acc[1][2]); acc[1][3] = ffma2(b1, a23.y, acc[1][3]);
                acc[2][0] = ffma2(b2, a01.x, acc[2][0]); acc[2][1] = ffma2(b2, a01.y, acc[2][1]);
                acc[2][2] = ffma2(b2, a23.x, acc[2][2]); acc[2][3] = ffma2(b2, a23.y, acc[2][3]);
                acc[3][0] = ffma2(b3, a01.x, acc[3][0]); acc[3][1] = ffma2(b3, a01.y, acc[3][1]);
                acc[3][2] = ffma2(b3, a23.x, acc[3][2]); acc[3][3] = ffma2(b3, a23.y, acc[3][3]);
            }
        }
        __syncthreads();
#pragma unroll
        for (int nn = 0; nn < 4; nn++) {
            int row = nt * 4 + nn;
#pragma unroll
            for (int mp = 0; mp < 4; mp++) {
                float lo, hi; unpack2(acc[nn][mp], lo, hi);
                *(u64*)(sAct + row * 132 + mt * 8 + mp * 2) = pack2f(fmaxf(lo, 0.f), fmaxf(hi, 0.f));
            }
        }
        __syncthreads();

        // ---- layer 2: thread tile 8M x 8N + relu + partial max ----
        u64 acc2[8][4];
#pragma unroll
        for (int nn = 0; nn < 8; nn++) {
            u64 bz = dup2(sB2[nt * 8 + nn]);
            acc2[nn][0] = bz; acc2[nn][1] = bz; acc2[nn][2] = bz; acc2[nn][3] = bz;
        }
        {
            const ulonglong2* A = (const ulonglong2*)(sAct + mt * 8);
            const float4* Bw = (const float4*)(sW2 + nt * 8);
#pragma unroll
            for (int k = 0; k < 64; k++) {
                ulonglong2 a01 = A[k * 33], a23 = A[k * 33 + 1];
                float4 w04 = Bw[k * 32], w48 = Bw[k * 32 + 1];
                u64 b0 = dup2(w04.x), b1 = dup2(w04.y), b2 = dup2(w04.z), b3 = dup2(w04.w);
                u64 b4 = dup2(w48.x), b5 = dup2(w48.y), b6 = dup2(w48.z), b7 = dup2(w48.w);
                acc2[0][0] = ffma2(b0, a01.x, acc2[0][0]); acc2[0][1] = ffma2(b0, a01.y, acc2[0][1]);
                acc2[0][2] = ffma2(b0, a23.x, acc2[0][2]); acc2[0][3] = ffma2(b0, a23.y, acc2[0][3]);
                acc2[1][0] = ffma2(b1, a01.x, acc2[1][0]); acc2[1][1] = ffma2(b1, a01.y, acc2[1][1]);
                acc2[1][2] = ffma2(b1, a23.x, acc2[1][2]); acc2[1][3] = ffma2(b1, a23.y, acc2[1][3]);
                acc2[2][0] = ffma2(b2, a01.x, acc2[2][0]); acc2[2][1] = ffma2(b2, a01.y, acc2[2][1]);
                acc2[2][2] = ffma2(b2, a23.x, acc2[2][2]); acc2[2][3] = ffma2(b2, a23.y, acc2[2][3]);
                acc2[3][0] = ffma2(b3, a01.x, acc2[3][0]); acc2[3][1] = ffma2(b3, a01.y, acc2[3][1]);
                acc2[3][2] = ffma2(b3, a23.x, acc2[3][2]); acc2[3][3] = ffma2(b3, a23.y, acc2[3][3]);
                acc2[4][0] = ffma2(b4, a01.x, acc2[4][0]); acc2[4][1] = ffma2(b4, a01.y, acc2[4][1]);
                acc2[4][2] = ffma2(b4, a23.x, acc2[4][2]); acc2[4][3] = ffma2(b4, a23.y, acc2[4][3]);
                acc2[5][0] = ffma2(b5, a01.x, acc2[5][0]); acc2[5][1] = ffma2(b5, a01.y, acc2[5][1]);
                acc2[5][2] = ffma2(b5, a23.x, acc2[5][2]); acc2[5][3] = ffma2(b5, a23.y, acc2[5][3]);
                acc2[6][0] = ffma2(b6, a01.x, acc2[6][0]); acc2[6][1] = ffma2(b6, a01.y, acc2[6][1]);
                acc2[6][2] = ffma2(b6, a23.x, acc2[6][2]); acc2[6][3] = ffma2(b6, a23.y, acc2[6][3]);
                acc2[7][0] = ffma2(b7, a01.x, acc2[7][0]); acc2[7][1] = ffma2(b7, a01.y, acc2[7][1]);
                acc2[7][2] = ffma2(b7, a23.x, acc2[7][2]); acc2[7][3] = ffma2(b7, a23.y, acc2[7][3]);
            }
        }
#pragma unroll
        for (int nn = 0; nn < 8; nn++) {
            float mm = -1e30f;
#pragma unroll
            for (int mp = 0; mp < 4; mp++) {
                float lo, hi; unpack2(acc2[nn][mp], lo, hi);
                mm = fmaxf(mm, fmaxf(lo, hi));
            }
            sPmax[mt * 128 + nt * 8 + nn] = fmaxf(mm, 0.f);
        }
        __syncthreads();
        if (t < 128) {
            int ch = t;
            float4 v;
            v.x = fmaxf(fmaxf(sPmax[ 0 * 128 + ch], sPmax[ 1 * 128 + ch]),
                        fmaxf(sPmax[ 2 * 128 + ch], sPmax[ 3 * 128 + ch]));
            v.y = fmaxf(fmaxf(sPmax[ 4 * 128 + ch], sPmax[ 5 * 128 + ch]),
                        fmaxf(sPmax[ 6 * 128 + ch], sPmax[ 7 * 128 + ch]));
            v.z = fmaxf(fmaxf(sPmax[ 8 * 128 + ch], sPmax[ 9 * 128 + ch]),
                        fmaxf(sPmax[10 * 128 + ch], sPmax[11 * 128 + ch]));
            v.w = fmaxf(fmaxf(sPmax[12 * 128 + ch], sPmax[13 * 128 + ch]),
                        fmaxf(sPmax[14 * 128 + ch], sPmax[15 * 128 + ch]));
            *(float4*)(out + (size_t)NB * NS * 3 + ((size_t)(b * 128 + ch)) * NS + s0) = v;
        }
        __syncthreads();   // protect smem reuse + sMisc for next chunk
    }
}

// ---------------- mega kernel: 16 FPS blocks + workers, one launch ----------------
__global__ __launch_bounds__(256) void mega_kernel(
    const float* __restrict__ xyz, const float* __restrict__ points, float* __restrict__ out)
{
    if (blockIdx.x < NB) {
        fps_phase(xyz, out);
        __syncthreads();
    }
    worker_main(xyz, points, out);   // FPS blocks drain the tail after finishing
}

// ---------------- launch ----------------
extern "C" void kernel_launch(void* const* d_in, const int* in_sizes, int n_in,
                              void* d_out, int out_size)
{
    const float* xyz = (const float*)d_in[0];
    const float* points = (const float*)d_in[1];
    const float* w0 = (const float*)d_in[2];
    const float* cb0 = (const float*)d_in[3];
    const float* g0 = (const float*)d_in[4];
    const float* b0 = (const float*)d_in[5];
    const float* m0 = (const float*)d_in[6];
    const float* v0 = (const float*)d_in[7];
    const float* w1 = (const float*)d_in[8];
    const float* cb1 = (const float*)d_in[9];
    const float* g1 = (const float*)d_in[10];
    const float* b1 = (const float*)d_in[11];
    const float* m1 = (const float*)d_in[12];
    const float* v1 = (const float*)d_in[13];
    const float* w2 = (const float*)d_in[14];
    const float* cb2 = (const float*)d_in[15];
    const float* g2 = (const float*)d_in[16];
    const float* b2 = (const float*)d_in[17];
    const float* m2 = (const float*)d_in[18];
    const float* v2 = (const float*)d_in[19];
    float* out = (float*)d_out;

    cudaFuncSetAttribute(mega_kernel, cudaFuncAttributeMaxDynamicSharedMemorySize, SMEMB);

    prep_kernel<<<1, 128>>>(w0, cb0, g0, b0, m0, v0,
                            w1, cb1, g1, b1, m1, v1,
                            w2, cb2, g2, b2, m2, v2);
    mega_kernel<<<NBLOCKS, 256, SMEMB>>>(xyz, points, out);
}

// round 4
// speedup vs baseline: 1.3085x; 1.3085x over previous
#include <cuda_runtime.h>

typedef unsigned long long u64;
typedef unsigned int u32;

#define NB 16
#define NPT 4096
#define NS 1024
#define NK 32
#define NCHUNKS 4096      /* (NB*NS)/4 centroid-chunks */
#define P0SLABS 128       /* 65536 points / 512 per slab */
#define NBLOCKS 148
#define NTHR 512

// ---- shared memory layout (floats) ----
#define OFF_W1    0        /* 4096 */
#define OFF_W2    4096     /* 8192 */
#define OFF_B1    12288    /* 64  (aliased by FPS sKey; FPS loads weights after) */
#define OFF_B2    12352    /* 128 */
#define OFF_W0X   12480    /* 192 */
#define OFF_GRP   12672    /* per-group regions */
#define GRP_STRIDE 10672
#define GOFF_ACT   0       /* 8448 = 64 x 132 ; group0 ACT also holds W0p+B0 during P0 */
#define GOFF_PMAX  8448    /* 2048 */
#define GOFF_IDX   10496   /* 128 ints */
#define GOFF_KKEY  10624   /* 16 u64 = 32 floats */
#define GOFF_MISC  10656   /* 8 u32 */
#define SMEM_FLOATS (OFF_GRP + 2 * GRP_STRIDE)   /* 34016 */
#define SMEMB (SMEM_FLOATS * 4)                  /* 136064 B -> 1 block/SM */

// ---------------- device scratch ----------------
__device__ __align__(16) float g_P0[NB * NPT * 64];
__device__ __align__(16) float g_W0x[3 * 64];
__device__ __align__(16) float g_W0p[64 * 64];
__device__ __align__(16) float g_B0[64];
__device__ __align__(16) float g_W1[64 * 64];
__device__ __align__(16) float g_B1[64];
__device__ __align__(16) float g_W2[64 * 128];
__device__ __align__(16) float g_B2[128];
__device__ int g_prog[NB];
__device__ u32 g_chunk;
__device__ u32 g_p0chunk;
__device__ u32 g_p0fin;

// ---------------- helpers ----------------
__device__ __forceinline__ u64 ffma2(u64 a, u64 b, u64 c) {
    u64 d; asm("fma.rn.f32x2 %0, %1, %2, %3;" : "=l"(d) : "l"(a), "l"(b), "l"(c)); return d;
}
__device__ __forceinline__ u64 add2(u64 a, u64 b) {
    u64 d; asm("add.rn.f32x2 %0, %1, %2;" : "=l"(d) : "l"(a), "l"(b)); return d;
}
__device__ __forceinline__ u64 mul2(u64 a, u64 b) {
    u64 d; asm("mul.rn.f32x2 %0, %1, %2;" : "=l"(d) : "l"(a), "l"(b)); return d;
}
__device__ __forceinline__ u64 dup2(float x) {
    u64 r; asm("mov.b64 %0, {%1, %1};" : "=l"(r) : "f"(x)); return r;
}
__device__ __forceinline__ u64 pack2f(float lo, float hi) {
    u64 r; asm("mov.b64 %0, {%1, %2};" : "=l"(r) : "f"(lo), "f"(hi)); return r;
}
__device__ __forceinline__ u64 packkey(u32 lo, u32 hi) {
    u64 r; asm("mov.b64 %0, {%1, %2};" : "=l"(r) : "r"(lo), "r"(hi)); return r;
}
__device__ __forceinline__ void unpack2(u64 a, float& lo, float& hi) {
    asm("mov.b64 {%0, %1}, %2;" : "=f"(lo), "=f"(hi) : "l"(a));
}
__device__ __forceinline__ void barn(int id, int cnt) {
    asm volatile("bar.sync %0, %1;" :: "r"(id), "r"(cnt) : "memory");
}

extern __shared__ float dynbuf[];

// ---------------- kernel 1: fold BN into weights + reset counters ----------------
__global__ void prep_kernel(
    const float* w0, const float* cb0, const float* g0, const float* b0, const float* m0, const float* v0,
    const float* w1, const float* cb1, const float* g1, const float* b1, const float* m1, const float* v1,
    const float* w2, const float* cb2, const float* g2, const float* b2, const float* m2, const float* v2)
{
    int o = threadIdx.x;
    if (o == 0) { g_chunk = 0; g_p0chunk = 0; g_p0fin = 0; }
    if (o < NB) g_prog[o] = 0;
    if (o < 64) {
        float s0 = g0[o] / sqrtf(v0[o] + 1e-5f);
        g_B0[o] = (cb0[o] - m0[o]) * s0 + b0[o];
        for (int i = 0; i < 3; i++)  g_W0x[i * 64 + o] = w0[o * 67 + i] * s0;
        for (int c = 0; c < 64; c++) g_W0p[c * 64 + o] = w0[o * 67 + 3 + c] * s0;
        float s1 = g1[o] / sqrtf(v1[o] + 1e-5f);
        g_B1[o] = (cb1[o] - m1[o]) * s1 + b1[o];
        for (int i = 0; i < 64; i++) g_W1[i * 64 + o] = w1[o * 64 + i] * s1;
    }
    if (o < 128) {
        float s2 = g2[o] / sqrtf(v2[o] + 1e-5f);
        g_B2[o] = (cb2[o] - m2[o]) * s2 + b2[o];
        for (int i = 0; i < 64; i++) g_W2[i * 128 + o] = w2[o * 64 + i] * s2;
    }
}

// ---------------- FPS phase (blocks 0..15), 512 threads ----------------
__device__ void fps_phase(const float* __restrict__ xyz, float* __restrict__ out_newxyz)
{
    float* sX = dynbuf;
    float* sY = dynbuf + NPT;
    float* sZ = dynbuf + 2 * NPT;
    u64* sKey = (u64*)(dynbuf + 3 * NPT);   // [2][16]

    int b = blockIdx.x, t = threadIdx.x;
    const float* xb = xyz + (size_t)b * NPT * 3;

    float fx[8], fy[8], fz[8], dd[8];
    u32 nlo[8];
#pragma unroll
    for (int j = 0; j < 8; j++) {
        int n = t + NTHR * j;
        fx[j] = xb[n * 3 + 0]; fy[j] = xb[n * 3 + 1]; fz[j] = xb[n * 3 + 2];
        sX[n] = fx[j]; sY[n] = fy[j]; sZ[n] = fz[j];
        dd[j] = 1e10f;
        nlo[j] = ~(u32)n;
    }
    u64 PX[4], PY[4], PZ[4];
#pragma unroll
    for (int jp = 0; jp < 4; jp++) {
        PX[jp] = pack2f(fx[2 * jp], fx[2 * jp + 1]);
        PY[jp] = pack2f(fy[2 * jp], fy[2 * jp + 1]);
        PZ[jp] = pack2f(fz[2 * jp], fz[2 * jp + 1]);
    }
    __syncthreads();

    float cx = sX[0], cy = sY[0], cz = sZ[0];
    if (t == 0) {
        float* o0 = out_newxyz + (size_t)b * NS * 3;
        o0[0] = cx; o0[1] = cy; o0[2] = cz;
    }

    int lane = t & 31, w = t >> 5;
    for (int it = 0; it < NS - 1; it++) {
        u64 ncx = dup2(-cx), ncy = dup2(-cy), ncz = dup2(-cz);
        u64 best = 0;
#pragma unroll
        for (int jp = 0; jp < 4; jp++) {
            // IEEE-identical to reference: (dx^2 + dy^2) + dz^2, round-to-nearest, no contraction
            u64 ax = add2(PX[jp], ncx); u64 sx = mul2(ax, ax);
            u64 ay = add2(PY[jp], ncy); u64 sy = mul2(ay, ay);
            u64 az = add2(PZ[jp], ncz); u64 sz = mul2(az, az);
            u64 s = add2(add2(sx, sy), sz);
            float da, db_; unpack2(s, da, db_);
            float n0 = fminf(dd[2 * jp], da);      dd[2 * jp] = n0;
            float n1 = fminf(dd[2 * jp + 1], db_); dd[2 * jp + 1] = n1;
            u64 k0 = packkey(nlo[2 * jp], __float_as_uint(n0));
            u64 k1 = packkey(nlo[2 * jp + 1], __float_as_uint(n1));
            u64 km = (k0 > k1) ? k0 : k1;
            best = (km > best) ? km : best;
        }
        // warp argmax
        u32 hi = (u32)(best >> 32);
        u32 H = __reduce_max_sync(0xffffffffu, hi);
        u32 cand = (hi == H) ? (u32)best : 0u;
        u32 L = __reduce_max_sync(0xffffffffu, cand);
        if (lane == 0) sKey[(it & 1) * 16 + w] = ((u64)H << 32) | (u64)L;
        __syncthreads();
        // second stage: lanes 0..15 of every warp hold the 16 warp keys, redux again
        u64 k2 = (lane < 16) ? sKey[(it & 1) * 16 + (lane & 15)] : 0ull;
        u32 h2 = (u32)(k2 >> 32);
        u32 H2 = __reduce_max_sync(0xffffffffu, h2);
        u32 c2 = (h2 == H2) ? (u32)k2 : 0u;
        u32 L2 = __reduce_max_sync(0xffffffffu, c2);
        int n = (int)((~L2) & (NPT - 1));
        cx = sX[n]; cy = sY[n]; cz = sZ[n];
        if (t == 0) {
            float* oo = out_newxyz + ((size_t)b * NS + it + 1) * 3;
            oo[0] = cx; oo[1] = cy; oo[2] = cz;
            if (((it + 2) & 3) == 0) {
                __threadfence();
                *(volatile int*)&g_prog[b] = it + 2;
            }
        }
    }
}

// ---------------- KNN for one centroid (128-thread subgroup, named barrier) ----------------
__device__ __forceinline__ void knn_one(
    const float* __restrict__ xyz, const float* __restrict__ out,
    int b, int cent, int barid, int tl, u64* sK /* 2x4 */, int* idxout)
{
    int sgc = b * NS + cent;
    float cx = __ldcg(out + (size_t)sgc * 3 + 0);
    float cy = __ldcg(out + (size_t)sgc * 3 + 1);
    float cz = __ldcg(out + (size_t)sgc * 3 + 2);
    const float* xb = xyz + (size_t)b * NPT * 3;

    float d[32];
#pragma unroll
    for (int j = 0; j < 32; j++) {
        int n = tl + 128 * j;
        float dx = __ldg(xb + n * 3 + 0) - cx;
        float dy = __ldg(xb + n * 3 + 1) - cy;
        float dz = __ldg(xb + n * 3 + 2) - cz;
        d[j] = __fadd_rn(__fadd_rn(__fmul_rn(dx, dx), __fmul_rn(dy, dy)), __fmul_rn(dz, dz));
    }
    u64 lk = ~0ull;
#pragma unroll
    for (int j = 0; j < 32; j++) {
        u64 key = ((u64)__float_as_uint(d[j]) << 32) | (u32)(tl + 128 * j);
        lk = (key < lk) ? key : lk;
    }
    int lane = tl & 31, w = tl >> 5;
    for (int r = 0; r < NK; r++) {
        u32 hi = (u32)(lk >> 32);
        u32 H = __reduce_min_sync(0xffffffffu, hi);
        u32 cand = (hi == H) ? (u32)lk : 0xffffffffu;
        u32 L = __reduce_min_sync(0xffffffffu, cand);
        if (lane == 0) sK[(r & 1) * 4 + w] = ((u64)H << 32) | (u64)L;
        barn(barid, 128);
        u64 gg = sK[(r & 1) * 4];
#pragma unroll
        for (int q = 1; q < 4; q++) { u64 k2 = sK[(r & 1) * 4 + q]; gg = (k2 < gg) ? k2 : gg; }
        if (tl == 0) idxout[r] = (int)((u32)gg);
        if (lk == gg) {
#pragma unroll
            for (int j = 0; j < 32; j++) {
                u64 key = ((u64)__float_as_uint(d[j]) << 32) | (u32)(tl + 128 * j);
                if (key == gg) d[j] = __uint_as_float(0x7f800000u);
            }
            lk = ~0ull;
#pragma unroll
            for (int j = 0; j < 32; j++) {
                u64 key = ((u64)__float_as_uint(d[j]) << 32) | (u32)(tl + 128 * j);
                lk = (key < lk) ? key : lk;
            }
        }
    }
}

// ---------------- mega kernel ----------------
__global__ __launch_bounds__(NTHR) void mega_kernel(
    const float* __restrict__ xyz, const float* __restrict__ points, float* __restrict__ out)
{
    int t = threadIdx.x;

    if (blockIdx.x < NB) {
        fps_phase(xyz, out);
        __syncthreads();
    }

    // ---- load weights into shared ----
    float* sW1  = dynbuf + OFF_W1;
    float* sW2  = dynbuf + OFF_W2;
    float* sB1  = dynbuf + OFF_B1;
    float* sB2  = dynbuf + OFF_B2;
    float* sW0x = dynbuf + OFF_W0X;
    float* pW0p = dynbuf + OFF_GRP;          // group0 ACT area, used only during P0
    for (int i = t; i < 4096; i += NTHR) sW1[i] = g_W1[i];
    for (int i = t; i < 8192; i += NTHR) sW2[i] = g_W2[i];
    for (int i = t; i < 4096; i += NTHR) pW0p[i] = g_W0p[i];
    if (t < 64)  sB1[t] = g_B1[t];
    if (t < 128) sB2[t] = g_B2[t];
    if (t < 192) sW0x[t] = g_W0x[t];
    if (t < 64)  pW0p[4096 + t] = g_B0[t];
    __syncthreads();

    // ---- P0: work-stolen slabs of 512 points (whole block) ----
    {
        volatile u32* sMisc0 = (volatile u32*)(dynbuf + OFF_GRP + GOFF_MISC);
        for (;;) {
            if (t == 0) sMisc0[1] = atomicAdd(&g_p0chunk, 1);
            __syncthreads();
            u32 slab = sMisc0[1];
            if (slab >= P0SLABS) break;
            int pid = (int)slab * NTHR + t;
            u64 acc[32];
            const u64* bb = (const u64*)(pW0p + 4096);
#pragma unroll
            for (int q = 0; q < 32; q++) acc[q] = bb[q];
            const float4* prr = (const float4*)(points + (size_t)pid * 64);
#pragma unroll
            for (int cc = 0; cc < 4; cc++) {
                float xr[16];
#pragma unroll
                for (int q = 0; q < 4; q++) {
                    float4 v = __ldg(prr + cc * 4 + q);
                    xr[4 * q + 0] = v.x; xr[4 * q + 1] = v.y; xr[4 * q + 2] = v.z; xr[4 * q + 3] = v.w;
                }
#pragma unroll
                for (int c = 0; c < 16; c++) {
                    u64 xi = dup2(xr[c]);
                    const ulonglong2* wr = (const ulonglong2*)(pW0p + (cc * 16 + c) * 64);
#pragma unroll
                    for (int q = 0; q < 16; q++) {
                        ulonglong2 wv = wr[q];
                        acc[2 * q]     = ffma2(xi, wv.x, acc[2 * q]);
                        acc[2 * q + 1] = ffma2(xi, wv.y, acc[2 * q + 1]);
                    }
                }
            }
            ulonglong2* op = (ulonglong2*)(g_P0 + (size_t)pid * 64);
#pragma unroll
            for (int q = 0; q < 16; q++) op[q] = make_ulonglong2(acc[2 * q], acc[2 * q + 1]);
            __threadfence();
            __syncthreads();
            if (t == 0) atomicAdd(&g_p0fin, 1);
        }
        if (t == 0) { while (*(volatile u32*)&g_p0fin < (u32)P0SLABS) __nanosleep(128); }
        __syncthreads();
        __threadfence();
    }

    // ---- split into 2 independent groups of 256 ----
    int g = t >> 8, tg = t & 255;
    float* gb   = dynbuf + OFF_GRP + g * GRP_STRIDE;
    float* sAct  = gb + GOFF_ACT;
    float* sPmax = gb + GOFF_PMAX;
    int*   sIdx  = (int*)(gb + GOFF_IDX);
    u64*   sKb   = (u64*)(gb + GOFF_KKEY);
    volatile u32* sMisc = (volatile u32*)(gb + GOFF_MISC);
    int GBAR = 1 + g;

    for (;;) {
        if (tg == 0) sMisc[0] = atomicAdd(&g_chunk, 1);
        barn(GBAR, 256);
        u32 c = sMisc[0];
        if (c >= NCHUNKS) break;
        int b = (int)(c & (NB - 1));
        int s0 = (int)(c >> 4) * 4;
        if (tg == 0) { while (*(volatile int*)&g_prog[b] < s0 + 4) __nanosleep(128); }
        barn(GBAR, 256);
        __threadfence();

        // ---- KNN: 2 subgroups x 128 threads, 2 centroids each ----
        {
            int sub = tg >> 7, tl = tg & 127;
            int barid = 3 + g * 2 + sub;
            for (int ci = 0; ci < 2; ci++) {
                int cl = sub * 2 + ci;
                knn_one(xyz, out, b, s0 + cl, barid, tl, sKb + sub * 8, sIdx + cl * 32);
            }
        }
        barn(GBAR, 256);

        // ---- layer 0 -> sAct[64][132] ----
        {
            int p = tg & 127, h = tg >> 7;
            int sgp = b * NS + s0 + (p >> 5);
            int n = sIdx[p];
            float ccx = __ldcg(out + (size_t)sgp * 3 + 0);
            float ccy = __ldcg(out + (size_t)sgp * 3 + 1);
            float ccz = __ldcg(out + (size_t)sgp * 3 + 2);
            const float* xp = xyz + ((size_t)b * NPT + n) * 3;
            float gx = xp[0] - ccx, gy = xp[1] - ccy, gz = xp[2] - ccz;
            u64 dgx = dup2(gx), dgy = dup2(gy), dgz = dup2(gz);
            const ulonglong2* pr  = (const ulonglong2*)(g_P0 + ((size_t)b * NPT + n) * 64 + h * 32);
            const ulonglong2* wxa = (const ulonglong2*)(sW0x + h * 32);
            const ulonglong2* wxb = (const ulonglong2*)(sW0x + 64 + h * 32);
            const ulonglong2* wxc = (const ulonglong2*)(sW0x + 128 + h * 32);
#pragma unroll
            for (int q = 0; q < 8; q++) {
                ulonglong2 pv = pr[q];
                ulonglong2 wa = wxa[q], wb = wxb[q], wc = wxc[q];
                u64 a0 = ffma2(dgx, wa.x, pv.x); a0 = ffma2(dgy, wb.x, a0); a0 = ffma2(dgz, wc.x, a0);
                u64 a1 = ffma2(dgx, wa.y, pv.y); a1 = ffma2(dgy, wb.y, a1); a1 = ffma2(dgz, wc.y, a1);
                float v0, v1, v2, v3;
                unpack2(a0, v0, v1); unpack2(a1, v2, v3);
                int j0 = h * 32 + q * 4;
                sAct[(j0 + 0) * 132 + p] = fmaxf(v0, 0.f);
                sAct[(j0 + 1) * 132 + p] = fmaxf(v1, 0.f);
                sAct[(j0 + 2) * 132 + p] = fmaxf(v2, 0.f);
                sAct[(j0 + 3) * 132 + p] = fmaxf(v3, 0.f);
            }
        }
        barn(GBAR, 256);

        int mt = tg >> 4, nt = tg & 15;

        // ---- layer 1: thread tile 8M x 4N ----
        u64 acc[4][4];
#pragma unroll
        for (int nn = 0; nn < 4; nn++) {
            u64 bz = dup2(sB1[nt * 4 + nn]);
            acc[nn][0] = bz; acc[nn][1] = bz; acc[nn][2] = bz; acc[nn][3] = bz;
        }
        {
            const ulonglong2* A  = (const ulonglong2*)(sAct + mt * 8);
            const float4* Bw = (const float4*)(sW1 + nt * 4);
#pragma unroll
            for (int k = 0; k < 64; k++) {
                ulonglong2 a01 = A[k * 33], a23 = A[k * 33 + 1];
                float4 bw = Bw[k * 16];
                u64 b0 = dup2(bw.x), b1 = dup2(bw.y), b2 = dup2(bw.z), b3 = dup2(bw.w);
                acc[0][0] = ffma2(b0, a01.x, acc[0][0]); acc[0][1] = ffma2(b0, a01.y, acc[0][1]);
                acc[0][2] = ffma2(b0, a23.x, acc[0][2]); acc[0][3] = ffma2(b0, a23.y, acc[0][3]);
                acc[1][0] = ffma2(b1, a01.x, acc[1][0]); acc[1][1] = ffma2(b1, a01.y, acc[1][1]);
                acc[1][2] = ffma2(b1, a23.x, acc[1][2]); acc[1][3] = ffma2(b1, a23.y, acc[1][3]);
                acc[2][0] = ffma2(b2, a01.x, acc[2][0]); acc[2][1] = ffma2(b2, a01.y, acc[2][1]);
                acc[2][2] = ffma2(b2, a23.x, acc[2][2]); acc[2][3] = ffma2(b2, a23.y, acc[2][3]);
                acc[3][0] = ffma2(b3, a01.x, acc[3][0]); acc[3][1] = ffma2(b3, a01.y, acc[3][1]);
                acc[3][2] = ffma2(b3, a23.x, acc[3][2]); acc[3][3] = ffma2(b3, a23.y, acc[3][3]);
            }
        }
        barn(GBAR, 256);
#pragma unroll
        for (int nn = 0; nn < 4; nn++) {
            int row = nt * 4 + nn;
#pragma unroll
            for (int mp = 0; mp < 4; mp++) {
                float lo, hi; unpack2(acc[nn][mp], lo, hi);
                *(u64*)(sAct + row * 132 + mt * 8 + mp * 2) = pack2f(fmaxf(lo, 0.f), fmaxf(hi, 0.f));
            }
        }
        barn(GBAR, 256);

        // ---- layer 2: thread tile 8M x 8N + relu + partial max ----
        u64 acc2[8][4];
#pragma unroll
        for (int nn = 0; nn < 8; nn++) {
            u64 bz = dup2(sB2[nt * 8 + nn]);
            acc2[nn][0] = bz; acc2[nn][1] = bz; acc2[nn][2] = bz; acc2[nn][3] = bz;
        }
        {
            const ulonglong2* A = (const ulonglong2*)(sAct + mt * 8);
            const float4* Bw = (const float4*)(sW2 + nt * 8);
#pragma unroll
            for (int k = 0; k < 64; k++) {
                ulonglong2 a01 = A[k * 33], a23 = A[k * 33 + 1];
                float4 w04 = Bw[k * 32], w48 = Bw[k * 32 + 1];
                u64 b0 = dup2(w04.x), b1 = dup2(w04.y), b2 = dup2(w04.z), b3 = dup2(w04.w);
                u64 b4 = dup2(w48.x), b5 = dup2(w48.y), b6 = dup2(w48.z), b7 = dup2(w48.w);
                acc2[0][0] = ffma2(b0, a01.x, acc2[0][0]); acc2[0][1] = ffma2(b0, a01.y, acc2[0][1]);
                acc2[0][2] = ffma2(b0, a23.x, acc2[0][2]); acc2[0][3] = ffma2(b0, a23.y, acc2[0][3]);
                acc2[1][0] = ffma2(b1, a01.x, acc2[1][0]); acc2[1][1] = ffma2(b1, a01.y, acc2[1][1]);
                acc2[1][2] = ffma2(b1, a23.x, acc2[1][2]); acc2[1][3] = ffma2(b1, a23.y, acc2[1][3]);
                acc2[2][0] = ffma2(b2, a01.x, acc2[2][0]); acc2[2][1] = ffma2(b2, a01.y, acc2[2][1]);
                acc2[2][2] = ffma2(b2, a23.x, acc2[2][2]); acc2[2][3] = ffma2(b2, a23.y, acc2[2][3]);
                acc2[3][0] = ffma2(b3, a01.x, acc2[3][0]); acc2[3][1] = ffma2(b3, a01.y, acc2[3][1]);
                acc2[3][2] = ffma2(b3, a23.x, acc2[3][2]); acc2[3][3] = ffma2(b3, a23.y, acc2[3][3]);
                acc2[4][0] = ffma2(b4, a01.x, acc2[4][0]); acc2[4][1] = ffma2(b4, a01.y, acc2[4][1]);
                acc2[4][2] = ffma2(b4, a23.x, acc2[4][2]); acc2[4][3] = ffma2(b4, a23.y, acc2[4][3]);
                acc2[5][0] = ffma2(b5, a01.x, acc2[5][0]); acc2[5][1] = ffma2(b5, a01.y, acc2[5][1]);
                acc2[5][2] = ffma2(b5, a23.x, acc2[5][2]); acc2[5][3] = ffma2(b5, a23.y, acc2[5][3]);
                acc2[6][0] = ffma2(b6, a01.x, acc2[6][0]); acc2[6][1] = ffma2(b6, a01.y, acc2[6][1]);
                acc2[6][2] = ffma2(b6, a23.x, acc2[6][2]); acc2[6][3] = ffma2(b6, a23.y, acc2[6][3]);
                acc2[7][0] = ffma2(b7, a01.x, acc2[7][0]); acc2[7][1] = ffma2(b7, a01.y, acc2[7][1]);
                acc2[7][2] = ffma2(b7, a23.x, acc2[7][2]); acc2[7][3] = ffma2(b7, a23.y, acc2[7][3]);
            }
        }
#pragma unroll
        for (int nn = 0; nn < 8; nn++) {
            float mm = -1e30f;
#pragma unroll
            for (int mp = 0; mp < 4; mp++) {
                float lo, hi; unpack2(acc2[nn][mp], lo, hi);
                mm = fmaxf(mm, fmaxf(lo, hi));
            }
            sPmax[mt * 128 + nt * 8 + nn] = fmaxf(mm, 0.f);
        }
        barn(GBAR, 256);
        if (tg < 128) {
            int ch = tg;
            float4 v;
            v.x = fmaxf(fmaxf(sPmax[ 0 * 128 + ch], sPmax[ 1 * 128 + ch]),
                        fmaxf(sPmax[ 2 * 128 + ch], sPmax[ 3 * 128 + ch]));
            v.y = fmaxf(fmaxf(sPmax[ 4 * 128 + ch], sPmax[ 5 * 128 + ch]),
                        fmaxf(sPmax[ 6 * 128 + ch], sPmax[ 7 * 128 + ch]));
            v.z = fmaxf(fmaxf(sPmax[ 8 * 128 + ch], sPmax[ 9 * 128 + ch]),
                        fmaxf(sPmax[10 * 128 + ch], sPmax[11 * 128 + ch]));
            v.w = fmaxf(fmaxf(sPmax[12 * 128 + ch], sPmax[13 * 128 + ch]),
                        fmaxf(sPmax[14 * 128 + ch], sPmax[15 * 128 + ch]));
            *(float4*)(out + (size_t)NB * NS * 3 + ((size_t)(b * 128 + ch)) * NS + s0) = v;
        }
        barn(GBAR, 256);
    }
}

// ---------------- launch ----------------
extern "C" void kernel_launch(void* const* d_in, const int* in_sizes, int n_in,
                              void* d_out, int out_size)
{
    const float* xyz = (const float*)d_in[0];
    const float* points = (const float*)d_in[1];
    const float* w0 = (const float*)d_in[2];
    const float* cb0 = (const float*)d_in[3];
    const float* g0 = (const float*)d_in[4];
    const float* b0 = (const float*)d_in[5];
    const float* m0 = (const float*)d_in[6];
    const float* v0 = (const float*)d_in[7];
    const float* w1 = (const float*)d_in[8];
    const float* cb1 = (const float*)d_in[9];
    const float* g1 = (const float*)d_in[10];
    const float* b1 = (const float*)d_in[11];
    const float* m1 = (const float*)d_in[12];
    const float* v1 = (const float*)d_in[13];
    const float* w2 = (const float*)d_in[14];
    const float* cb2 = (const float*)d_in[15];
    const float* g2 = (const float*)d_in[16];
    const float* b2 = (const float*)d_in[17];
    const float* m2 = (const float*)d_in[18];
    const float* v2 = (const float*)d_in[19];
    float* out = (float*)d_out;

    cudaFuncSetAttribute(mega_kernel, cudaFuncAttributeMaxDynamicSharedMemorySize, SMEMB);

    prep_kernel<<<1, 128>>>(w0, cb0, g0, b0, m0, v0,
                            w1, cb1, g1, b1, m1, v1,
                            w2, cb2, g2, b2, m2, v2);
    mega_kernel<<<NBLOCKS, NTHR, SMEMB>>>(xyz, points, out);
}